// round 2
// baseline (speedup 1.0000x reference)
#include <cuda_runtime.h>
#include <cuda_bf16.h>
#include <math.h>

// Rigid-warp + trilinear resample of a 256^3 fp32 volume.
// d_in: [0] image [1,1,256,256,256] f32, [1] rotation [1,3], [2] translation [1,3],
//       [3] ref_v2r [4,4], [4] flo_v2r [4,4].  out: [1,1,256,256,256] f32.

#define DIMD 256
#define DIMH 256
#define DIMW 256

__device__ float g_T[12];

__device__ __forceinline__ void matmul3(const float a[9], const float b[9], float c[9]) {
    #pragma unroll
    for (int i = 0; i < 3; i++)
        #pragma unroll
        for (int j = 0; j < 3; j++)
            c[i * 3 + j] = a[i * 3 + 0] * b[0 * 3 + j]
                         + a[i * 3 + 1] * b[1 * 3 + j]
                         + a[i * 3 + 2] * b[2 * 3 + j];
}

__device__ __forceinline__ void matmul4(const float a[16], const float b[16], float c[16]) {
    #pragma unroll
    for (int i = 0; i < 4; i++)
        #pragma unroll
        for (int j = 0; j < 4; j++)
            c[i * 4 + j] = a[i * 4 + 0] * b[0 * 4 + j]
                         + a[i * 4 + 1] * b[1 * 4 + j]
                         + a[i * 4 + 2] * b[2 * 4 + j]
                         + a[i * 4 + 3] * b[3 * 4 + j];
}

__device__ void inv4(const float m[16], float invOut[16]) {
    float inv[16];
    inv[0]  =  m[5]*m[10]*m[15] - m[5]*m[11]*m[14] - m[9]*m[6]*m[15] +
               m[9]*m[7]*m[14]  + m[13]*m[6]*m[11] - m[13]*m[7]*m[10];
    inv[4]  = -m[4]*m[10]*m[15] + m[4]*m[11]*m[14] + m[8]*m[6]*m[15] -
               m[8]*m[7]*m[14]  - m[12]*m[6]*m[11] + m[12]*m[7]*m[10];
    inv[8]  =  m[4]*m[9]*m[15]  - m[4]*m[11]*m[13] - m[8]*m[5]*m[15] +
               m[8]*m[7]*m[13]  + m[12]*m[5]*m[11] - m[12]*m[7]*m[9];
    inv[12] = -m[4]*m[9]*m[14]  + m[4]*m[10]*m[13] + m[8]*m[5]*m[14] -
               m[8]*m[6]*m[13]  - m[12]*m[5]*m[10] + m[12]*m[6]*m[9];
    inv[1]  = -m[1]*m[10]*m[15] + m[1]*m[11]*m[14] + m[9]*m[2]*m[15] -
               m[9]*m[3]*m[14]  - m[13]*m[2]*m[11] + m[13]*m[3]*m[10];
    inv[5]  =  m[0]*m[10]*m[15] - m[0]*m[11]*m[14] - m[8]*m[2]*m[15] +
               m[8]*m[3]*m[14]  + m[12]*m[2]*m[11] - m[12]*m[3]*m[10];
    inv[9]  = -m[0]*m[9]*m[15]  + m[0]*m[11]*m[13] + m[8]*m[1]*m[15] -
               m[8]*m[3]*m[13]  - m[12]*m[1]*m[11] + m[12]*m[3]*m[9];
    inv[13] =  m[0]*m[9]*m[14]  - m[0]*m[10]*m[13] - m[8]*m[1]*m[14] +
               m[8]*m[2]*m[13]  + m[12]*m[1]*m[10] - m[12]*m[2]*m[9];
    inv[2]  =  m[1]*m[6]*m[15]  - m[1]*m[7]*m[14]  - m[5]*m[2]*m[15] +
               m[5]*m[3]*m[14]  + m[13]*m[2]*m[7]  - m[13]*m[3]*m[6];
    inv[6]  = -m[0]*m[6]*m[15]  + m[0]*m[7]*m[14]  + m[4]*m[2]*m[15] -
               m[4]*m[3]*m[14]  - m[12]*m[2]*m[7]  + m[12]*m[3]*m[6];
    inv[10] =  m[0]*m[5]*m[15]  - m[0]*m[7]*m[13]  - m[4]*m[1]*m[15] +
               m[4]*m[3]*m[13]  + m[12]*m[1]*m[7]  - m[12]*m[3]*m[5];
    inv[14] = -m[0]*m[5]*m[14]  + m[0]*m[6]*m[13]  + m[4]*m[1]*m[14] -
               m[4]*m[2]*m[13]  - m[12]*m[1]*m[6]  + m[12]*m[2]*m[5];
    inv[3]  = -m[1]*m[6]*m[11]  + m[1]*m[7]*m[10]  + m[5]*m[2]*m[11] -
               m[5]*m[3]*m[10]  - m[9]*m[2]*m[7]   + m[9]*m[3]*m[6];
    inv[7]  =  m[0]*m[6]*m[11]  - m[0]*m[7]*m[10]  - m[4]*m[2]*m[11] +
               m[4]*m[3]*m[10]  + m[8]*m[2]*m[7]   - m[8]*m[3]*m[6];
    inv[11] = -m[0]*m[5]*m[11]  + m[0]*m[7]*m[9]   + m[4]*m[1]*m[11] -
               m[4]*m[3]*m[9]   - m[8]*m[1]*m[7]   + m[8]*m[3]*m[5];
    inv[15] =  m[0]*m[5]*m[10]  - m[0]*m[6]*m[9]   - m[4]*m[1]*m[10] +
               m[4]*m[2]*m[9]   + m[8]*m[1]*m[6]   - m[8]*m[2]*m[5];

    float det = m[0]*inv[0] + m[1]*inv[4] + m[2]*inv[8] + m[3]*inv[12];
    det = 1.0f / det;
    #pragma unroll
    for (int i = 0; i < 16; i++) invOut[i] = inv[i] * det;
}

__global__ void compute_transform_kernel(const float* __restrict__ rot,
                                         const float* __restrict__ tra,
                                         const float* __restrict__ ref_v2r,
                                         const float* __restrict__ flo_v2r) {
    float cx = cosf(rot[0]), cy = cosf(rot[1]), cz = cosf(rot[2]);
    float sx = sinf(rot[0]), sy = sinf(rot[1]), sz = sinf(rot[2]);

    float Rx[9] = {1, 0, 0,  0, cx, -sx,  0, sx, cx};
    float Ry[9] = {cy, 0, sy,  0, 1, 0,  -sy, 0, cy};
    float Rz[9] = {cz, -sz, 0,  sz, cz, 0,  0, 0, 1};
    float RxRy[9], R[9];
    matmul3(Rx, Ry, RxRy);
    matmul3(RxRy, Rz, R);

    float Trig[16] = {
        R[0], R[1], R[2], tra[0],
        R[3], R[4], R[5], tra[1],
        R[6], R[7], R[8], tra[2],
        0.f,  0.f,  0.f,  1.f
    };

    float ref[16], flo[16];
    #pragma unroll
    for (int i = 0; i < 16; i++) { ref[i] = ref_v2r[i]; flo[i] = flo_v2r[i]; }

    float flo_inv[16], A[16], T[16];
    inv4(flo, flo_inv);
    matmul4(Trig, ref, A);
    matmul4(flo_inv, A, T);

    #pragma unroll
    for (int i = 0; i < 12; i++) g_T[i] = T[i];
}

// Select value at position off (0..3) from the window {p.x, p.y, q.x, q.y}.
__device__ __forceinline__ float pick4(float2 p, float2 q, int off) {
    float v01 = (off == 0) ? p.x : p.y;
    float v23 = (off == 2) ? q.x : q.y;
    return (off < 2) ? v01 : v23;
}

__global__ void __launch_bounds__(256)
warp_trilinear2_kernel(const float* __restrict__ X, float2* __restrict__ out2) {
    const int pid = blockIdx.x * 256 + threadIdx.x;   // pair index
    const int kA  = (pid & 127) << 1;                 // k of output A (even)
    const int j   = (pid >> 7) & 255;
    const int i   = pid >> 15;

    const float T00 = g_T[0], T01 = g_T[1], T02 = g_T[2],  T03 = g_T[3];
    const float T10 = g_T[4], T11 = g_T[5], T12 = g_T[6],  T13 = g_T[7];
    const float T20 = g_T[8], T21 = g_T[9], T22 = g_T[10], T23 = g_T[11];

    const float fi = (float)i, fj = (float)j;
    const float fkA = (float)kA, fkB = (float)(kA + 1);

    const float diA = fmaf(T00, fi, fmaf(T01, fj, fmaf(T02, fkA, T03)));
    const float djA = fmaf(T10, fi, fmaf(T11, fj, fmaf(T12, fkA, T13)));
    const float dkA = fmaf(T20, fi, fmaf(T21, fj, fmaf(T22, fkA, T23)));
    const float diB = fmaf(T00, fi, fmaf(T01, fj, fmaf(T02, fkB, T03)));
    const float djB = fmaf(T10, fi, fmaf(T11, fj, fmaf(T12, fkB, T13)));
    const float dkB = fmaf(T20, fi, fmaf(T21, fj, fmaf(T22, fkB, T23)));

    const float MX = 255.f;
    const bool okA = (diA > 0.f) & (djA > 0.f) & (dkA > 0.f) &
                     (diA <= MX) & (djA <= MX) & (dkA <= MX);
    const bool okB = (diB > 0.f) & (djB > 0.f) & (dkB > 0.f) &
                     (diB <= MX) & (djB <= MX) & (dkB <= MX);

    // A weights / indices (clamped for address safety)
    const float fxA = floorf(diA), fyA = floorf(djA), fzA = floorf(dkA);
    const float wcxA = diA - fxA, wfxA = 1.f - wcxA;
    const float wcyA = djA - fyA, wfyA = 1.f - wcyA;
    const float wczA = dkA - fzA, wfzA = 1.f - wczA;
    const int x0A = (int)fminf(fmaxf(fxA, 0.f), MX);
    const int y0A = (int)fminf(fmaxf(fyA, 0.f), MX);
    const int z0A = (int)fminf(fmaxf(fzA, 0.f), MX);
    const int x1A = min(x0A + 1, 255);
    const int y1A = min(y0A + 1, 255);
    const int z1A = min(z0A + 1, 255);

    // B weights / indices
    const float fxB = floorf(diB), fyB = floorf(djB), fzB = floorf(dkB);
    const float wcxB = diB - fxB, wfxB = 1.f - wcxB;
    const float wcyB = djB - fyB, wfyB = 1.f - wcyB;
    const float wczB = dkB - fzB, wfzB = 1.f - wczB;
    const int x0B = (int)fminf(fmaxf(fxB, 0.f), MX);
    const int y0B = (int)fminf(fmaxf(fyB, 0.f), MX);
    const int z0B = (int)fminf(fmaxf(fzB, 0.f), MX);
    const int x1B = min(x0B + 1, 255);
    const int y1B = min(y0B + 1, 255);
    const int z1B = min(z0B + 1, 255);

    // Shared z window base: use only valid outputs' z (invalid ones can be wild).
    const int z0Ae = okA ? z0A : (okB ? z0B : 0);
    const int z0Be = okB ? z0B : z0Ae;
    const int e = min(min(z0Ae, z0Be) & ~1, 252);

    const int offA0 = z0A - e, offA1 = z1A - e;
    const int offB0 = z0B - e, offB1 = z1B - e;

    const bool same = (x0A == x0B) & (y0A == y0B);

    // row base offsets (floats)
    const int rA00 = (x0A << 16) | (y0A << 8);
    const int rA01 = (x0A << 16) | (y1A << 8);
    const int rA10 = (x1A << 16) | (y0A << 8);
    const int rA11 = (x1A << 16) | (y1A << 8);
    const int rB00 = (x0B << 16) | (y0B << 8);
    const int rB01 = (x0B << 16) | (y1B << 8);
    const int rB10 = (x1B << 16) | (y0B << 8);
    const int rB11 = (x1B << 16) | (y1B << 8);

    const float wA00 = wfxA * wfyA, wA01 = wfxA * wcyA;
    const float wA10 = wcxA * wfyA, wA11 = wcxA * wcyA;
    const float wB00 = wfxB * wfyB, wB01 = wfxB * wcyB;
    const float wB10 = wcxB * wfyB, wB11 = wcxB * wcyB;

    float accA = 0.f, accB = 0.f;

    #define DO_ROW(RA, RB, WA, WB)                                              \
    {                                                                           \
        const float2 p = __ldg((const float2*)(X + (RA) + e));                  \
        const float2 q = __ldg((const float2*)(X + (RA) + e + 2));              \
        const float vA0 = pick4(p, q, offA0);                                   \
        const float vA1 = pick4(p, q, offA1);                                   \
        accA = fmaf(fmaf(vA0, wfzA, vA1 * wczA), (WA), accA);                   \
        float vB0, vB1;                                                         \
        if (same) {                                                             \
            vB0 = pick4(p, q, offB0);                                           \
            vB1 = pick4(p, q, offB1);                                           \
        } else {                                                                \
            vB0 = __ldg(X + (RB) + z0B);                                        \
            vB1 = __ldg(X + (RB) + z1B);                                        \
        }                                                                       \
        accB = fmaf(fmaf(vB0, wfzB, vB1 * wczB), (WB), accB);                   \
    }

    DO_ROW(rA00, rB00, wA00, wB00);
    DO_ROW(rA01, rB01, wA01, wB01);
    DO_ROW(rA10, rB10, wA10, wB10);
    DO_ROW(rA11, rB11, wA11, wB11);
    #undef DO_ROW

    float2 res;
    res.x = okA ? accA : 0.f;
    res.y = okB ? accB : 0.f;
    out2[pid] = res;
}

extern "C" void kernel_launch(void* const* d_in, const int* in_sizes, int n_in,
                              void* d_out, int out_size) {
    const float* image = (const float*)d_in[0];
    const float* rot   = (const float*)d_in[1];
    const float* tra   = (const float*)d_in[2];
    const float* refm  = (const float*)d_in[3];
    const float* flom  = (const float*)d_in[4];

    compute_transform_kernel<<<1, 1>>>(rot, tra, refm, flom);

    const int n_pairs = (DIMD * DIMH * DIMW) / 2;       // 2^23
    warp_trilinear2_kernel<<<n_pairs / 256, 256>>>(image, (float2*)d_out);
}

// round 4
// speedup vs baseline: 1.1809x; 1.1809x over previous
#include <cuda_runtime.h>
#include <cuda_bf16.h>
#include <math.h>

// Rigid-warp + trilinear resample of a 256^3 fp32 volume.
// d_in: [0] image [1,1,256,256,256] f32, [1] rotation [1,3], [2] translation [1,3],
//       [3] ref_v2r [4,4], [4] flo_v2r [4,4].  out: [1,1,256,256,256] f32.

#define DIMD 256
#define DIMH 256
#define DIMW 256

__device__ float g_T[12];

__device__ __forceinline__ void matmul3(const float a[9], const float b[9], float c[9]) {
    #pragma unroll
    for (int i = 0; i < 3; i++)
        #pragma unroll
        for (int j = 0; j < 3; j++)
            c[i * 3 + j] = a[i * 3 + 0] * b[0 * 3 + j]
                         + a[i * 3 + 1] * b[1 * 3 + j]
                         + a[i * 3 + 2] * b[2 * 3 + j];
}

__device__ __forceinline__ void matmul4(const float a[16], const float b[16], float c[16]) {
    #pragma unroll
    for (int i = 0; i < 4; i++)
        #pragma unroll
        for (int j = 0; j < 4; j++)
            c[i * 4 + j] = a[i * 4 + 0] * b[0 * 4 + j]
                         + a[i * 4 + 1] * b[1 * 4 + j]
                         + a[i * 4 + 2] * b[2 * 4 + j]
                         + a[i * 4 + 3] * b[3 * 4 + j];
}

__device__ void inv4(const float m[16], float invOut[16]) {
    float inv[16];
    inv[0]  =  m[5]*m[10]*m[15] - m[5]*m[11]*m[14] - m[9]*m[6]*m[15] +
               m[9]*m[7]*m[14]  + m[13]*m[6]*m[11] - m[13]*m[7]*m[10];
    inv[4]  = -m[4]*m[10]*m[15] + m[4]*m[11]*m[14] + m[8]*m[6]*m[15] -
               m[8]*m[7]*m[14]  - m[12]*m[6]*m[11] + m[12]*m[7]*m[10];
    inv[8]  =  m[4]*m[9]*m[15]  - m[4]*m[11]*m[13] - m[8]*m[5]*m[15] +
               m[8]*m[7]*m[13]  + m[12]*m[5]*m[11] - m[12]*m[7]*m[9];
    inv[12] = -m[4]*m[9]*m[14]  + m[4]*m[10]*m[13] + m[8]*m[5]*m[14] -
               m[8]*m[6]*m[13]  - m[12]*m[5]*m[10] + m[12]*m[6]*m[9];
    inv[1]  = -m[1]*m[10]*m[15] + m[1]*m[11]*m[14] + m[9]*m[2]*m[15] -
               m[9]*m[3]*m[14]  - m[13]*m[2]*m[11] + m[13]*m[3]*m[10];
    inv[5]  =  m[0]*m[10]*m[15] - m[0]*m[11]*m[14] - m[8]*m[2]*m[15] +
               m[8]*m[3]*m[14]  + m[12]*m[2]*m[11] - m[12]*m[3]*m[10];
    inv[9]  = -m[0]*m[9]*m[15]  + m[0]*m[11]*m[13] + m[8]*m[1]*m[15] -
               m[8]*m[3]*m[13]  - m[12]*m[1]*m[11] + m[12]*m[3]*m[9];
    inv[13] =  m[0]*m[9]*m[14]  - m[0]*m[10]*m[13] - m[8]*m[1]*m[14] +
               m[8]*m[2]*m[13]  + m[12]*m[1]*m[10] - m[12]*m[2]*m[9];
    inv[2]  =  m[1]*m[6]*m[15]  - m[1]*m[7]*m[14]  - m[5]*m[2]*m[15] +
               m[5]*m[3]*m[14]  + m[13]*m[2]*m[7]  - m[13]*m[3]*m[6];
    inv[6]  = -m[0]*m[6]*m[15]  + m[0]*m[7]*m[14]  + m[4]*m[2]*m[15] -
               m[4]*m[3]*m[14]  - m[12]*m[2]*m[7]  + m[12]*m[3]*m[6];
    inv[10] =  m[0]*m[5]*m[15]  - m[0]*m[7]*m[13]  - m[4]*m[1]*m[15] +
               m[4]*m[3]*m[13]  + m[12]*m[1]*m[7]  - m[12]*m[3]*m[5];
    inv[14] = -m[0]*m[5]*m[14]  + m[0]*m[6]*m[13]  + m[4]*m[1]*m[14] -
               m[4]*m[2]*m[13]  - m[12]*m[1]*m[6]  + m[12]*m[2]*m[5];
    inv[3]  = -m[1]*m[6]*m[11]  + m[1]*m[7]*m[10]  + m[5]*m[2]*m[11] -
               m[5]*m[3]*m[10]  - m[9]*m[2]*m[7]   + m[9]*m[3]*m[6];
    inv[7]  =  m[0]*m[6]*m[11]  - m[0]*m[7]*m[10]  - m[4]*m[2]*m[11] +
               m[4]*m[3]*m[10]  + m[8]*m[2]*m[7]   - m[8]*m[3]*m[6];
    inv[11] = -m[0]*m[5]*m[11]  + m[0]*m[7]*m[9]   + m[4]*m[1]*m[11] -
               m[4]*m[3]*m[9]   - m[8]*m[1]*m[7]   + m[8]*m[3]*m[5];
    inv[15] =  m[0]*m[5]*m[10]  - m[0]*m[6]*m[9]   - m[4]*m[1]*m[10] +
               m[4]*m[2]*m[9]   + m[8]*m[1]*m[6]   - m[8]*m[2]*m[5];

    float det = m[0]*inv[0] + m[1]*inv[4] + m[2]*inv[8] + m[3]*inv[12];
    det = 1.0f / det;
    #pragma unroll
    for (int i = 0; i < 16; i++) invOut[i] = inv[i] * det;
}

__global__ void compute_transform_kernel(const float* __restrict__ rot,
                                         const float* __restrict__ tra,
                                         const float* __restrict__ ref_v2r,
                                         const float* __restrict__ flo_v2r) {
    float cx = cosf(rot[0]), cy = cosf(rot[1]), cz = cosf(rot[2]);
    float sx = sinf(rot[0]), sy = sinf(rot[1]), sz = sinf(rot[2]);

    float Rx[9] = {1, 0, 0,  0, cx, -sx,  0, sx, cx};
    float Ry[9] = {cy, 0, sy,  0, 1, 0,  -sy, 0, cy};
    float Rz[9] = {cz, -sz, 0,  sz, cz, 0,  0, 0, 1};
    float RxRy[9], R[9];
    matmul3(Rx, Ry, RxRy);
    matmul3(RxRy, Rz, R);

    float Trig[16] = {
        R[0], R[1], R[2], tra[0],
        R[3], R[4], R[5], tra[1],
        R[6], R[7], R[8], tra[2],
        0.f,  0.f,  0.f,  1.f
    };

    float ref[16], flo[16];
    #pragma unroll
    for (int i = 0; i < 16; i++) { ref[i] = ref_v2r[i]; flo[i] = flo_v2r[i]; }

    float flo_inv[16], A[16], T[16];
    inv4(flo, flo_inv);
    matmul4(Trig, ref, A);
    matmul4(flo_inv, A, T);

    #pragma unroll
    for (int i = 0; i < 12; i++) g_T[i] = T[i];
}

__global__ void __launch_bounds__(256)
warp_trilinear_shfl_kernel(const float* __restrict__ X, float* __restrict__ out) {
    const int k = threadIdx.x;            // W (stride-1), warp = 32 consecutive k
    const int j = blockIdx.x & (DIMH - 1);
    const int i = blockIdx.x >> 8;        // D
    const int lane = k & 31;

    const float T00 = g_T[0], T01 = g_T[1], T02 = g_T[2],  T03 = g_T[3];
    const float T10 = g_T[4], T11 = g_T[5], T12 = g_T[6],  T13 = g_T[7];
    const float T20 = g_T[8], T21 = g_T[9], T22 = g_T[10], T23 = g_T[11];

    const float fi = (float)i, fj = (float)j, fk = (float)k;
    const float di = fmaf(T00, fi, fmaf(T01, fj, fmaf(T02, fk, T03)));
    const float dj = fmaf(T10, fi, fmaf(T11, fj, fmaf(T12, fk, T13)));
    const float dk = fmaf(T20, fi, fmaf(T21, fj, fmaf(T22, fk, T23)));

    const int idx = (i << 16) | (j << 8) | k;
    const float MX = 255.f;

    // strictly-interior mask (matches reference: >0 and <= dim-1)
    const bool ok = (di > 0.f) & (dj > 0.f) & (dk > 0.f) &
                    (di <= MX) & (dj <= MX) & (dk <= MX);

    const float fx = floorf(di), fy = floorf(dj), fz = floorf(dk);
    const float wcx = di - fx, wcy = dj - fy, wcz = dk - fz;
    const float wfx = 1.f - wcx, wfy = 1.f - wcy, wfz = 1.f - wcz;

    // clamp ALL indices (no early-out: warp must stay converged for shuffles)
    const int x0 = (int)fminf(fmaxf(fx, 0.f), MX);
    const int y0 = (int)fminf(fmaxf(fy, 0.f), MX);
    const int z0 = (int)fminf(fmaxf(fz, 0.f), MX);
    const int x1 = min(x0 + 1, 255);
    const int y1 = min(y0 + 1, 255);
    const int z1 = min(z0 + 1, 255);

    const int r00 = (x0 << 16) | (y0 << 8);
    const int r01 = (x0 << 16) | (y1 << 8);
    const int r10 = (x1 << 16) | (y0 << 8);
    const int r11 = (x1 << 16) | (y1 << 8);

    // Full base-voxel index of the (x0,y0,z0) tap. If lane+1's base index is
    // EXACTLY ours+1, then x0,y0 match and z0 advanced by 1 — so lane+1's four
    // primary taps are our four z1 taps (x1,y1 are monotone in x0,y0).
    const int idx0  = r00 + z0;
    const int idx0n = __shfl_down_sync(0xffffffffu, idx0, 1);
    const bool useShfl = (lane < 31) && (idx0n == idx0 + 1) && (z1 == z0 + 1);

    // 4 primary gathers (one per (x,y) row) — fire them all for MLP
    const float a00 = __ldg(X + r00 + z0);
    const float a01 = __ldg(X + r01 + z0);
    const float a10 = __ldg(X + r10 + z0);
    const float a11 = __ldg(X + r11 + z0);

    // z1 taps via shuffle (all lanes execute shuffles; fallback loads predicated)
    const float s00 = __shfl_down_sync(0xffffffffu, a00, 1);
    const float s01 = __shfl_down_sync(0xffffffffu, a01, 1);
    const float s10 = __shfl_down_sync(0xffffffffu, a10, 1);
    const float s11 = __shfl_down_sync(0xffffffffu, a11, 1);

    float b00, b01, b10, b11;
    if (useShfl) {
        b00 = s00; b01 = s01; b10 = s10; b11 = s11;
    } else {
        b00 = __ldg(X + r00 + z1);
        b01 = __ldg(X + r01 + z1);
        b10 = __ldg(X + r10 + z1);
        b11 = __ldg(X + r11 + z1);
    }

    // interpolate z, then y, then x
    const float c00 = fmaf(a00, wfz, b00 * wcz);
    const float c01 = fmaf(a01, wfz, b01 * wcz);
    const float c10 = fmaf(a10, wfz, b10 * wcz);
    const float c11 = fmaf(a11, wfz, b11 * wcz);

    const float c0 = fmaf(c00, wfy, c01 * wcy);
    const float c1 = fmaf(c10, wfy, c11 * wcy);
    const float v  = fmaf(c0, wfx, c1 * wcx);

    out[idx] = ok ? v : 0.f;
}

extern "C" void kernel_launch(void* const* d_in, const int* in_sizes, int n_in,
                              void* d_out, int out_size) {
    const float* image = (const float*)d_in[0];
    const float* rot   = (const float*)d_in[1];
    const float* tra   = (const float*)d_in[2];
    const float* refm  = (const float*)d_in[3];
    const float* flom  = (const float*)d_in[4];
    float* out = (float*)d_out;

    compute_transform_kernel<<<1, 1>>>(rot, tra, refm, flom);
    warp_trilinear_shfl_kernel<<<DIMD * DIMH, DIMW>>>(image, out);
}